// round 6
// baseline (speedup 1.0000x reference)
#include <cuda_runtime.h>
#include <cstdint>
#include <cstddef>

#define S_LEN 2048
#define BATCH 512
#define VDIM  29
#define HDIM  128
#define KTOT  160            // 128 (h) + 29 (x) padded to 160
#define NWARP 8
#define KC    (KTOT / NWARP) // 20 k's per warp
#define ROWS  2              // batch rows per CTA (2 CTAs co-resident per SM)
#define GDUP  (ROWS * 2)     // state stored duplicated: (h_r, h_r) pairs

// intermediate encoder state (static device scratch — no allocation)
__device__ float g_enc[BATCH * HDIM];

typedef unsigned long long ull;

__device__ __forceinline__ ull pack2(float lo, float hi) {
    ull r; asm("mov.b64 %0, {%1, %2};" : "=l"(r) : "f"(lo), "f"(hi)); return r;
}
__device__ __forceinline__ ull fma2(ull a, ull b, ull c) {
    ull d; asm("fma.rn.f32x2 %0, %1, %2, %3;" : "=l"(d) : "l"(a), "l"(b), "l"(c)); return d;
}
__device__ __forceinline__ void unpack2(ull v, float& lo, float& hi) {
    asm("mov.b64 {%0, %1}, %2;" : "=f"(lo), "=f"(hi) : "l"(v));
}

// ---------------------------------------------------------------------------
// Encoder: persistent kernel. 256 CTAs x 2 batch rows x 256 threads,
// 2 CTAs/SM so one CTA's GEMV hides the other's reduce/barrier bubble.
// Warp w owns k in [w*20, w*20+20); lane owns cols 4*lane..+3, weight
// col-pairs pre-packed in registers (wlo/whi). State g is kept DUPLICATED
// in SMEM as (h_r,h_r) so the f32x2 b-operand is a single LDS.64 (no MOVs).
// 8-way k-partials reduced via SMEM by all 256 threads.
// ---------------------------------------------------------------------------
__global__ void __launch_bounds__(256, 2) enc_kernel(
    const float* __restrict__ x, const float* __restrict__ We_ih,
    const float* __restrict__ We_hh, const float* __restrict__ be_ih,
    const float* __restrict__ be_hh)
{
    extern __shared__ float sm[];
    float* Wt    = sm;                        // [KTOT][HDIM] staging (dead after init)
    float* gb    = Wt + KTOT * HDIM;          // [2][KTOT][GDUP] double-buffered, dup'd
    float* red   = gb + 2 * KTOT * GDUP;      // [NWARP*ROWS][HDIM] partials
    float* biasE = red + NWARP * ROWS * HDIM; // [HDIM]

    const int tid  = threadIdx.x;
    const int warp = tid >> 5, lane = tid & 31;
    const int rowbase = blockIdx.x * ROWS;

    // Build k-major combined weight in SMEM, then lift col-pairs to registers
    for (int i = tid; i < KTOT * HDIM; i += 256) {
        int k = i >> 7, j = i & (HDIM - 1);
        float w = 0.f;
        if (k < HDIM)             w = We_hh[j * HDIM + k];
        else if (k < HDIM + VDIM) w = We_ih[j * VDIM + (k - HDIM)];
        Wt[i] = w;
    }
    if (tid < HDIM) biasE[tid] = be_ih[tid] + be_hh[tid];
    for (int i = tid; i < 2 * KTOT * GDUP; i += 256) gb[i] = 0.f;  // h=0, pads=0
    __syncthreads();

    const int k0 = warp * KC;
    ull wlo[KC], whi[KC];                      // pre-packed col pairs (80 regs)
    #pragma unroll
    for (int kk = 0; kk < KC; ++kk) {
        const float4 w4 = *(const float4*)(Wt + (k0 + kk) * HDIM + 4 * lane);
        wlo[kk] = pack2(w4.x, w4.y);
        whi[kk] = pack2(w4.z, w4.w);
    }

    // x_0 into buffer 0's x-region (duplicated pairs)
    if (tid < ROWS * VDIM) {
        int r = tid / VDIM, v = tid - r * VDIM;
        float xv = x[((size_t)(rowbase + r) * S_LEN) * VDIM + v];
        *(float2*)(gb + (HDIM + v) * GDUP + 2 * r) = make_float2(xv, xv);
    }
    __syncthreads();

    const int jred = tid & (HDIM - 1);         // finalize: 128 j x 2 rows
    const int rr   = tid >> 7;

    for (int t = 0; t < S_LEN; ++t) {
        float* g  = gb + (t & 1) * (KTOT * GDUP);
        float* gn = gb + ((t & 1) ^ 1) * (KTOT * GDUP);

        // prefetch next step's x (latency hidden under the GEMV)
        float xr = 0.f; int xslot = -1;
        if (tid < ROWS * VDIM && t + 1 < S_LEN) {
            int r = tid / VDIM, v = tid - r * VDIM;
            xr = x[((size_t)(rowbase + r) * S_LEN + (t + 1)) * VDIM + v];
            xslot = (HDIM + v) * GDUP + 2 * r;
        }

        ull aL0 = 0, aH0 = 0, aL1 = 0, aH1 = 0;   // row r, col-pairs (lo: c0c1, hi: c2c3)
        const float* gk = g + k0 * GDUP;
        #pragma unroll
        for (int kk = 0; kk < KC; ++kk) {
            const ull b0 = *(const ull*)(gk + kk * GDUP);      // (h0,h0) broadcast LDS.64
            const ull b1 = *(const ull*)(gk + kk * GDUP + 2);  // (h1,h1)
            aL0 = fma2(wlo[kk], b0, aL0); aH0 = fma2(whi[kk], b0, aH0);
            aL1 = fma2(wlo[kk], b1, aL1); aH1 = fma2(whi[kk], b1, aH1);
        }
        float q0, q1, q2, q3, q4, q5, q6, q7;
        unpack2(aL0, q0, q1); unpack2(aH0, q2, q3);
        unpack2(aL1, q4, q5); unpack2(aH1, q6, q7);
        {   // store k-partials, conflict-free STS.128
            float* rb = red + (warp * ROWS) * HDIM + 4 * lane;
            *(float4*)(rb)        = make_float4(q0, q1, q2, q3);
            *(float4*)(rb + HDIM) = make_float4(q4, q5, q6, q7);
        }
        if (xslot >= 0) *(float2*)(gn + xslot) = make_float2(xr, xr);
        __syncthreads();

        // finalize: 256 threads, each sums 8 partials for (j, row rr), tanh
        {
            float s = biasE[jred];
            #pragma unroll
            for (int kc = 0; kc < NWARP; ++kc)
                s += red[(kc * ROWS + rr) * HDIM + jred];
            float h = tanhf(s);
            *(float2*)(gn + jred * GDUP + 2 * rr) = make_float2(h, h);
            if (t == S_LEN - 1) g_enc[(rowbase + rr) * HDIM + jred] = h;
        }
        __syncthreads();
    }
}

// ---------------------------------------------------------------------------
// Decoder: one warp per batch row, 128 CTAs x 4 warps. dec_in is constant
// per row and the map h -> tanh(dec_in + W h) is a contraction, so in fp32
// it settles into an exactly periodic orbit (period 1 or 2) within ~100
// steps. Detect h_s == h_{s-2} BITWISE across the whole state (exact: once
// the state repeats, the sequence is periodic forever) and fill the tail
// with the alternating pair. Falls back to the full 2048 steps otherwise.
// ---------------------------------------------------------------------------
__global__ void __launch_bounds__(128) dec_kernel(
    const float* __restrict__ Wd_ih, const float* __restrict__ Wd_hh,
    const float* __restrict__ bd_ih, const float* __restrict__ bd_hh,
    float* __restrict__ out)
{
    const int warp = threadIdx.x >> 5, lane = threadIdx.x & 31;
    const int b = blockIdx.x * 4 + warp;
    const float* er = g_enc + b * HDIM;
    float e0 = er[lane], e1 = er[32 + lane], e2 = er[64 + lane], e3 = er[96 + lane];
    const bool act = lane < VDIM;
    const int vl = act ? lane : 0;   // clamp so inactive lanes do harmless loads

    float Wr[VDIM];
    #pragma unroll
    for (int u = 0; u < VDIM; ++u) Wr[u] = Wd_hh[vl * VDIM + u];

    float din = bd_ih[vl] + bd_hh[vl];
    {   // dec_in[v] = sum_k Wd_ih[v][k] * enc[b][k]
        const float* wi = Wd_ih + vl * HDIM;
        float s0 = 0, s1 = 0, s2 = 0, s3 = 0;
        #pragma unroll
        for (int k = 0; k < 32; ++k) {
            s0 += wi[k]      * __shfl_sync(0xffffffffu, e0, k);
            s1 += wi[32 + k] * __shfl_sync(0xffffffffu, e1, k);
            s2 += wi[64 + k] * __shfl_sync(0xffffffffu, e2, k);
            s3 += wi[96 + k] * __shfl_sync(0xffffffffu, e3, k);
        }
        din += (s0 + s1) + (s2 + s3);
    }

    float h  = 0.f;                              // h_{s-1}
    float hp = __int_as_float(0x7fc00000);       // h_{s-2} (NaN: never matches)
    float fillA = 0.f, fillB = 0.f;
    float* orow = out + (size_t)b * S_LEN * VDIM + lane;
    int s = 0;
    for (; s < S_LEN; ++s) {
        float q0 = din, q1 = 0.f, q2 = 0.f, q3 = 0.f;
        #pragma unroll
        for (int u = 0; u < 28; u += 4) {
            q0 += Wr[u]     * __shfl_sync(0xffffffffu, h, u);
            q1 += Wr[u + 1] * __shfl_sync(0xffffffffu, h, u + 1);
            q2 += Wr[u + 2] * __shfl_sync(0xffffffffu, h, u + 2);
            q3 += Wr[u + 3] * __shfl_sync(0xffffffffu, h, u + 3);
        }
        q0 += Wr[28] * __shfl_sync(0xffffffffu, h, 28);
        float hn = tanhf((q0 + q1) + (q2 + q3));   // h_s
        if (act) orow[(size_t)s * VDIM] = hn;
        bool eq = (!act) || (__float_as_int(hn) == __float_as_int(hp));
        bool periodic = __all_sync(0xffffffffu, eq);
        hp = h; h = hn;
        if (periodic) {                // h_s == h_{s-2}: period-2 orbit from here
            fillA = hp;                // h_{s+1} = h_{s-1}
            fillB = hn;                // h_{s+2} = h_s
            ++s; break;
        }
    }
    if (act) {
        for (; s + 1 < S_LEN; s += 2) {
            orow[(size_t)(s    ) * VDIM] = fillA;
            orow[(size_t)(s + 1) * VDIM] = fillB;
        }
        if (s < S_LEN) orow[(size_t)s * VDIM] = fillA;
    }
}

// ---------------------------------------------------------------------------
extern "C" void kernel_launch(void* const* d_in, const int* in_sizes, int n_in,
                              void* d_out, int out_size) {
    const float* x     = (const float*)d_in[0];
    const float* We_ih = (const float*)d_in[1];
    const float* We_hh = (const float*)d_in[2];
    const float* be_ih = (const float*)d_in[3];
    const float* be_hh = (const float*)d_in[4];
    const float* Wd_ih = (const float*)d_in[5];
    const float* Wd_hh = (const float*)d_in[6];
    const float* bd_ih = (const float*)d_in[7];
    const float* bd_hh = (const float*)d_in[8];
    float* out = (float*)d_out;

    const int smem = (KTOT * HDIM + 2 * KTOT * GDUP + NWARP * ROWS * HDIM + HDIM) * 4; // 95744 B
    cudaFuncSetAttribute(enc_kernel, cudaFuncAttributeMaxDynamicSharedMemorySize, smem);

    enc_kernel<<<BATCH / ROWS, 256, smem>>>(x, We_ih, We_hh, be_ih, be_hh);
    dec_kernel<<<BATCH / 4, 128>>>(Wd_ih, Wd_hh, bd_ih, bd_hh, out);
}

// round 7
// speedup vs baseline: 1.1124x; 1.1124x over previous
#include <cuda_runtime.h>
#include <cstdint>
#include <cstddef>

#define S_LEN 2048
#define BATCH 512
#define VDIM  29
#define HDIM  128
#define KTOT  160            // 128 (h) + 29 (x) padded to 160
#define NWARP 8              // k-split chunks
#define KC    (KTOT / NWARP) // 20 k's per chunk
#define ROWS  4              // batch rows per CTA (block=512, 1 CTA/SM, single wave)

// intermediate encoder state (static device scratch — no allocation)
__device__ float g_enc[BATCH * HDIM];

typedef unsigned long long ull;

__device__ __forceinline__ ull pack2(float lo, float hi) {
    ull r; asm("mov.b64 %0, {%1, %2};" : "=l"(r) : "f"(lo), "f"(hi)); return r;
}
__device__ __forceinline__ ull fma2(ull a, ull b, ull c) {
    ull d; asm("fma.rn.f32x2 %0, %1, %2, %3;" : "=l"(d) : "l"(a), "l"(b), "l"(c)); return d;
}
__device__ __forceinline__ void unpack2(ull v, float& lo, float& hi) {
    asm("mov.b64 {%0, %1}, %2;" : "=f"(lo), "=f"(hi) : "l"(v));
}

// ---------------------------------------------------------------------------
// Encoder: 128 CTAs x 4 batch rows x 512 threads (1 CTA/SM, single wave,
// uniform 4 rows/SM). Warp w (w&7 = k-chunk, w>>3 = row-pair) owns k in
// [chunk*20, chunk*20+20) for rows (rp*2, rp*2+1). Weight col-pairs live in
// registers; state g is stored DUPLICATED per row-pair as (h0,h0,h1,h1) so
// ONE LDS.128 per k feeds all four fma2 (zero MOVs). 8-way k-partials
// reduced in SMEM by all 512 threads (128 j x 4 rows).
// ---------------------------------------------------------------------------
__global__ void __launch_bounds__(512, 1) enc_kernel(
    const float* __restrict__ x, const float* __restrict__ We_ih,
    const float* __restrict__ We_hh, const float* __restrict__ be_ih,
    const float* __restrict__ be_hh)
{
    extern __shared__ float sm[];
    float* Wt    = sm;                        // [KTOT][HDIM] staging (dead after init)
    float* gb    = Wt + KTOT * HDIM;          // [2 buf][2 rowpair][KTOT][4]
    float* red   = gb + 2 * 2 * KTOT * 4;     // [NWARP][4 rows][HDIM] partials
    float* biasE = red + NWARP * 4 * HDIM;    // [HDIM]

    const int tid  = threadIdx.x;
    const int warp = tid >> 5, lane = tid & 31;
    const int chunk = warp & 7;                // k-chunk 0..7
    const int rp    = warp >> 3;               // 0: rows 0,1  1: rows 2,3
    const int rowbase = blockIdx.x * ROWS;

    // Build k-major combined weight in SMEM, then lift col-pairs to registers
    for (int i = tid; i < KTOT * HDIM; i += 512) {
        int k = i >> 7, j = i & (HDIM - 1);
        float w = 0.f;
        if (k < HDIM)             w = We_hh[j * HDIM + k];
        else if (k < HDIM + VDIM) w = We_ih[j * VDIM + (k - HDIM)];
        Wt[i] = w;
    }
    if (tid < HDIM) biasE[tid] = be_ih[tid] + be_hh[tid];
    for (int i = tid; i < 2 * 2 * KTOT * 4; i += 512) gb[i] = 0.f;  // h=0, pads=0
    __syncthreads();

    const int k0 = chunk * KC;
    ull wlo[KC], whi[KC];                      // pre-packed col pairs (80 regs)
    #pragma unroll
    for (int kk = 0; kk < KC; ++kk) {
        const float4 w4 = *(const float4*)(Wt + (k0 + kk) * HDIM + 4 * lane);
        wlo[kk] = pack2(w4.x, w4.y);
        whi[kk] = pack2(w4.z, w4.w);
    }

    // x_0 into buffer 0's x-region (duplicated pairs)
    if (tid < ROWS * VDIM) {
        int r = tid / VDIM, v = tid - r * VDIM;
        float xv = x[((size_t)(rowbase + r) * S_LEN) * VDIM + v];
        *(float2*)(gb + ((r >> 1) * KTOT + HDIM + v) * 4 + 2 * (r & 1)) =
            make_float2(xv, xv);
    }
    __syncthreads();

    const int jred = tid & (HDIM - 1);         // finalize: 128 j x 4 rows
    const int rr   = tid >> 7;                 // row 0..3

    for (int t = 0; t < S_LEN; ++t) {
        const int bo  = (t & 1) * (2 * KTOT * 4);
        const int bn  = ((t & 1) ^ 1) * (2 * KTOT * 4);

        // prefetch next step's x (latency hidden under the GEMV)
        float xr = 0.f; int xslot = -1;
        if (tid < ROWS * VDIM && t + 1 < S_LEN) {
            int r = tid / VDIM, v = tid - r * VDIM;
            xr = x[((size_t)(rowbase + r) * S_LEN + (t + 1)) * VDIM + v];
            xslot = bn + ((r >> 1) * KTOT + HDIM + v) * 4 + 2 * (r & 1);
        }

        ull aL0 = 0, aH0 = 0, aL1 = 0, aH1 = 0;  // rowpair, col-pairs lo/hi
        const float* gk = gb + bo + (rp * KTOT + k0) * 4;
        #pragma unroll
        for (int kk = 0; kk < KC; ++kk) {
            const ulonglong2 gg = *(const ulonglong2*)(gk + kk * 4); // 1 LDS.128
            aL0 = fma2(wlo[kk], gg.x, aL0); aH0 = fma2(whi[kk], gg.x, aH0);
            aL1 = fma2(wlo[kk], gg.y, aL1); aH1 = fma2(whi[kk], gg.y, aH1);
        }
        float q0, q1, q2, q3, q4, q5, q6, q7;
        unpack2(aL0, q0, q1); unpack2(aH0, q2, q3);
        unpack2(aL1, q4, q5); unpack2(aH1, q6, q7);
        {   // store k-partials, conflict-free STS.128
            float* rb = red + (chunk * 4 + rp * 2) * HDIM + 4 * lane;
            *(float4*)(rb)        = make_float4(q0, q1, q2, q3);
            *(float4*)(rb + HDIM) = make_float4(q4, q5, q6, q7);
        }
        if (xslot >= 0) *(float2*)(gb + xslot) = make_float2(xr, xr);
        __syncthreads();

        // finalize: 512 threads, each sums 8 partials for (j, row rr), tanh
        {
            float s = biasE[jred];
            #pragma unroll
            for (int kc = 0; kc < NWARP; ++kc)
                s += red[(kc * 4 + rr) * HDIM + jred];
            float h = tanhf(s);
            *(float2*)(gb + bn + ((rr >> 1) * KTOT + jred) * 4 + 2 * (rr & 1)) =
                make_float2(h, h);
            if (t == S_LEN - 1) g_enc[(rowbase + rr) * HDIM + jred] = h;
        }
        __syncthreads();
    }
}

// ---------------------------------------------------------------------------
// Decoder: one warp per batch row, 128 CTAs x 4 warps (1 warp/SMSP).
// No shuffles in the hot loop (SHFL is MIO-throughput-bound): h lives in a
// per-warp double-buffered SMEM slot; per step = 8 broadcast LDS.128 +
// 32 FMA + tanh + 1 STS + 1 syncwarp. W row padded to 32 with zeros so
// inactive lanes (29..31) are harmless.
// ---------------------------------------------------------------------------
__global__ void __launch_bounds__(128) dec_kernel(
    const float* __restrict__ Wd_ih, const float* __restrict__ Wd_hh,
    const float* __restrict__ bd_ih, const float* __restrict__ bd_hh,
    float* __restrict__ out)
{
    __shared__ float hbuf[2][4][32];
    const int warp = threadIdx.x >> 5, lane = threadIdx.x & 31;
    const int b = blockIdx.x * 4 + warp;
    const float* er = g_enc + b * HDIM;
    float e0 = er[lane], e1 = er[32 + lane], e2 = er[64 + lane], e3 = er[96 + lane];
    const bool act = lane < VDIM;
    const int vl = act ? lane : 0;   // clamp so inactive lanes do harmless loads

    float Wp[32];                    // padded Wd_hh row (zeros for u >= 29)
    #pragma unroll
    for (int u = 0; u < 32; ++u) Wp[u] = (u < VDIM) ? Wd_hh[vl * VDIM + u] : 0.f;

    float din = bd_ih[vl] + bd_hh[vl];
    {   // dec_in[v] = sum_k Wd_ih[v][k] * enc[b][k]   (one-time, shfl is fine)
        const float* wi = Wd_ih + vl * HDIM;
        float s0 = 0, s1 = 0, s2 = 0, s3 = 0;
        #pragma unroll
        for (int k = 0; k < 32; ++k) {
            s0 += wi[k]      * __shfl_sync(0xffffffffu, e0, k);
            s1 += wi[32 + k] * __shfl_sync(0xffffffffu, e1, k);
            s2 += wi[64 + k] * __shfl_sync(0xffffffffu, e2, k);
            s3 += wi[96 + k] * __shfl_sync(0xffffffffu, e3, k);
        }
        din += (s0 + s1) + (s2 + s3);
    }

    hbuf[0][warp][lane] = 0.f;       // h_0 = 0
    __syncwarp();

    float* orow = out + (size_t)b * S_LEN * VDIM + lane;
    for (int s = 0; s < S_LEN; ++s) {
        const float* hv = hbuf[s & 1][warp];
        float q0 = din, q1 = 0.f, q2 = 0.f, q3 = 0.f;
        #pragma unroll
        for (int i = 0; i < 8; ++i) {
            const float4 hh = *(const float4*)(hv + 4 * i);   // broadcast LDS.128
            q0 += Wp[4 * i]     * hh.x;
            q1 += Wp[4 * i + 1] * hh.y;
            q2 += Wp[4 * i + 2] * hh.z;
            q3 += Wp[4 * i + 3] * hh.w;
        }
        float hn = tanhf((q0 + q1) + (q2 + q3));
        hbuf[(s & 1) ^ 1][warp][lane] = hn;   // all lanes write; pads multiply by 0
        if (act) orow[(size_t)s * VDIM] = hn;
        __syncwarp();
    }
}

// ---------------------------------------------------------------------------
extern "C" void kernel_launch(void* const* d_in, const int* in_sizes, int n_in,
                              void* d_out, int out_size) {
    const float* x     = (const float*)d_in[0];
    const float* We_ih = (const float*)d_in[1];
    const float* We_hh = (const float*)d_in[2];
    const float* be_ih = (const float*)d_in[3];
    const float* be_hh = (const float*)d_in[4];
    const float* Wd_ih = (const float*)d_in[5];
    const float* Wd_hh = (const float*)d_in[6];
    const float* bd_ih = (const float*)d_in[7];
    const float* bd_hh = (const float*)d_in[8];
    float* out = (float*)d_out;

    const int smem = (KTOT * HDIM + 2 * 2 * KTOT * 4 + NWARP * 4 * HDIM + HDIM) * 4; // 109056 B
    cudaFuncSetAttribute(enc_kernel, cudaFuncAttributeMaxDynamicSharedMemorySize, smem);

    enc_kernel<<<BATCH / ROWS, 512, smem>>>(x, We_ih, We_hh, be_ih, be_hh);
    dec_kernel<<<BATCH / 4, 128>>>(Wd_ih, Wd_hh, bd_ih, bd_hh, out);
}